// round 14
// baseline (speedup 1.0000x reference)
#include <cuda_runtime.h>
#include <cuda_fp16.h>
#include <math.h>
#include <stdint.h>

// ---------------- problem constants ----------------
#define NB   3
#define Bc   4
#define Tt   512
#define Nf   256
#define Dd   1024
#define DXFc 512
#define Ee   1024
#define Hh   16
#define HDc  64
#define SQ   (NB*Tt)   // 1536
#define SKk  (NB*Nf)   // 768
#define BHc  (Bc*Hh)   // 64
#define EPSV 1e-6f

// ---------------- scratch (fp16 activations/weights) ----------------
__device__ float g_mod_x [NB*Bc*2*Dd];
__device__ float g_mod_xf[NB*Bc*2*DXFc];
__device__ __align__(16) __half g_xn [NB*Bc*Tt*Dd];
__device__ __align__(16) __half g_xfn[NB*Bc*Nf*DXFc];
__device__ __align__(16) __half g_Qh[(size_t)BHc*SQ*HDc];
__device__ __align__(16) __half g_Kh[(size_t)BHc*SKk*HDc];
__device__ __align__(16) __half g_Vh[(size_t)BHc*SKk*HDc];
__device__ __align__(16) __half g_att[(size_t)Bc*SQ*Dd];
__device__ __align__(16) __half g_qw[NB*Dd*Dd];
__device__ __align__(16) __half g_kw[NB*Dd*DXFc];
__device__ __align__(16) __half g_vw[NB*Dd*DXFc];
__device__ __align__(16) __half g_ow[NB*Dd*Dd];

// ---------------- helpers ----------------
__device__ __forceinline__ uint32_t pack16(float lo, float hi) {
    uint32_t r;
    asm("cvt.rn.f16x2.f32 %0, %1, %2;" : "=r"(r) : "f"(hi), "f"(lo));
    return r;
}
__device__ __forceinline__ void mma_f16(
    float& d0, float& d1, float& d2, float& d3,
    uint32_t a0, uint32_t a1, uint32_t a2, uint32_t a3,
    uint32_t b0, uint32_t b1)
{
    asm volatile(
        "mma.sync.aligned.m16n8k16.row.col.f32.f16.f16.f32 "
        "{%0,%1,%2,%3}, {%4,%5,%6,%7}, {%8,%9}, {%0,%1,%2,%3};"
        : "+f"(d0), "+f"(d1), "+f"(d2), "+f"(d3)
        : "r"(a0), "r"(a1), "r"(a2), "r"(a3), "r"(b0), "r"(b1));
}
__device__ __forceinline__ void cp_async16(void* dst, const void* src) {
    uint32_t s = (uint32_t)__cvta_generic_to_shared(dst);
    asm volatile("cp.async.cg.shared.global [%0], [%1], 16;" :: "r"(s), "l"(src));
}
#define CP_COMMIT() asm volatile("cp.async.commit_group;")
#define CP_WAIT0()  asm volatile("cp.async.wait_group 0;" ::: "memory")

// ---------------- kernel 0: convert ALL weights to fp16 ----------------
__global__ __launch_bounds__(256) void cvt_w_kernel(
    const float* __restrict__ qs, const float* __restrict__ ks,
    const float* __restrict__ vs, const float* __restrict__ os,
    __half* __restrict__ qd, __half* __restrict__ kd,
    __half* __restrict__ vd, __half* __restrict__ od)
{
    int y = blockIdx.y;
    const float* src; __half* dst; int n4;
    if (y == 0)      { src = qs; dst = qd; n4 = NB*Dd*Dd/4; }
    else if (y == 1) { src = ks; dst = kd; n4 = NB*Dd*DXFc/4; }
    else if (y == 2) { src = vs; dst = vd; n4 = NB*Dd*DXFc/4; }
    else             { src = os; dst = od; n4 = NB*Dd*Dd/4; }
    int i = blockIdx.x*256 + threadIdx.x;
    if (i < n4) {
        float4 v = ((const float4*)src)[i];
        uint2 o;
        o.x = pack16(v.x, v.y);
        o.y = pack16(v.z, v.w);
        ((uint2*)dst)[i] = o;
    }
}

// ---------------- kernel 1: adaLN modulation (both sets, one launch) ----------------
__global__ __launch_bounds__(256) void adaln_mod_kernel(
    const float* __restrict__ emb,
    const float* __restrict__ wx,  const float* __restrict__ bx,
    const float* __restrict__ wxf, const float* __restrict__ bxf,
    float* __restrict__ outx, float* __restrict__ outxf)
{
    int z = blockIdx.z;
    int isx = (z < NB);
    int n = isx ? z : z - NB;
    int twoD = isx ? 2*Dd : 2*DXFc;
    int j = blockIdx.x*256 + threadIdx.x;
    if (j >= twoD) return;
    const float* w    = isx ? wx   : wxf;
    const float* bvec = isx ? bx   : bxf;
    float* out        = isx ? outx : outxf;

    __shared__ float se[Ee];
    int b = blockIdx.y;
    int tid = threadIdx.x;
    for (int i = tid*4; i < Ee; i += 256*4) {
        float4 v = *(const float4*)(emb + (size_t)b*Ee + i);
        se[i+0] = v.x / (1.f + __expf(-v.x));
        se[i+1] = v.y / (1.f + __expf(-v.y));
        se[i+2] = v.z / (1.f + __expf(-v.z));
        se[i+3] = v.w / (1.f + __expf(-v.w));
    }
    __syncthreads();
    const float* wr = w + ((size_t)n*twoD + j)*Ee;
    float acc = 0.f;
    #pragma unroll 8
    for (int e = 0; e < Ee; e += 4) {
        float4 wv = *(const float4*)(wr + e);
        acc += se[e]*wv.x + se[e+1]*wv.y + se[e+2]*wv.z + se[e+3]*wv.w;
    }
    out[((size_t)n*Bc + b)*twoD + j] = acc + bvec[(size_t)n*twoD + j];
}

// ---------------- kernel 2: LayerNorm + modulate -> fp16 (both sets) ----------------
__global__ __launch_bounds__(256) void ln_mod_kernel(
    const float* __restrict__ x1, const float* __restrict__ x2,
    const float* __restrict__ x3,
    const float* __restrict__ xf1, const float* __restrict__ xf2,
    const float* __restrict__ xf3,
    const float* __restrict__ modx, const float* __restrict__ modxf,
    __half* __restrict__ xn, __half* __restrict__ xfn)
{
    int r = blockIdx.x;
    int dim, n, b;
    const float* xp;
    const float* mod;
    __half* op;
    if (r < NB*Bc*Tt) {
        dim = Dd;
        n = r / (Bc*Tt);
        int rr = r - n*(Bc*Tt);
        b = rr / Tt;
        xp = (n == 0 ? x1 : (n == 1 ? x2 : x3)) + (size_t)rr*dim;
        mod = modx + ((size_t)n*Bc + b)*2*dim;
        op = xn + (size_t)r*dim;
    } else {
        int r2 = r - NB*Bc*Tt;
        dim = DXFc;
        n = r2 / (Bc*Nf);
        int rr = r2 - n*(Bc*Nf);
        b = rr / Nf;
        xp = (n == 0 ? xf1 : (n == 1 ? xf2 : xf3)) + (size_t)rr*dim;
        mod = modxf + ((size_t)n*Bc + b)*2*dim;
        op = xfn + (size_t)r2*dim;
    }
    int tid = threadIdx.x;

    float s1 = 0.f, s2 = 0.f;
    for (int d = tid*4; d < dim; d += 1024) {
        float4 v = *(const float4*)(xp + d);
        s1 += v.x + v.y + v.z + v.w;
        s2 += v.x*v.x + v.y*v.y + v.z*v.z + v.w*v.w;
    }
    #pragma unroll
    for (int off = 16; off; off >>= 1) {
        s1 += __shfl_xor_sync(0xffffffffu, s1, off);
        s2 += __shfl_xor_sync(0xffffffffu, s2, off);
    }
    __shared__ float rs1[8], rs2[8];
    int wid = tid >> 5, lane = tid & 31;
    if (!lane) { rs1[wid] = s1; rs2[wid] = s2; }
    __syncthreads();
    s1 = rs1[0]+rs1[1]+rs1[2]+rs1[3]+rs1[4]+rs1[5]+rs1[6]+rs1[7];
    s2 = rs2[0]+rs2[1]+rs2[2]+rs2[3]+rs2[4]+rs2[5]+rs2[6]+rs2[7];

    float inv = 1.f / (float)dim;
    float mu  = s1 * inv;
    float var = s2 * inv - mu*mu;
    float rstd = rsqrtf(var + EPSV);

    const float* sc = mod;
    const float* sh = mod + dim;
    for (int d = tid*4; d < dim; d += 1024) {
        float4 v = *(const float4*)(xp + d);
        float4 s = *(const float4*)(sc + d);
        float4 h = *(const float4*)(sh + d);
        uint2 o;
        o.x = pack16((v.x - mu)*rstd*(1.f + s.x) + h.x,
                     (v.y - mu)*rstd*(1.f + s.y) + h.y);
        o.y = pack16((v.z - mu)*rstd*(1.f + s.z) + h.z,
                     (v.w - mu)*rstd*(1.f + s.w) + h.w);
        *(uint2*)(op + d) = o;
    }
}

// ---------------- kernel 3: fp16 GEMM, tile 128x64, 3 CTAs/SM ----------------
// 256 thr, 8 warps in 2x4 grid; warp tile 64x16 (MI=4, NI=2) => 32 acc regs.
// k-slab 64 halves (32 words), 2-stage cp.async.
#define GW_STRIDE 40                 // words per smem row (32 + 8 pad)
#define GA_TILEW (128*GW_STRIDE)     // A tile words
#define GB_TILEW (64*GW_STRIDE)      // B tile words
#define GSTAGEW  (GA_TILEW + GB_TILEW)
#define GEMM_SMEM (2*GSTAGEW*4)      // 61440 bytes

// MODE 0: A rows [M][K] fp16 (pre-offset to block n); C = fp16 head-layout, scaled.
// MODE 1: A = g_att rows (bq*NB+n)*L+tq fp16; C = fp32 [n][Bc*Tt][Dd] (d_out).
template<int MODE>
__device__ __forceinline__ void gemm_body(
    const __half* __restrict__ A, const __half* __restrict__ W,
    const float* __restrict__ bias, void* __restrict__ C,
    int Kdim, int L, int n, int mt, int nt, float oscale)
{
    extern __shared__ uint32_t gsw[];
    int tid = threadIdx.x;
    int m0 = mt*128;

    // A loader: 2 thr/row x 16 words; B loader: 4 thr/row x 8 words (64 rows)
    int arow = tid >> 1, acw = (tid & 1) * 16;
    int brow = tid >> 2, bcw = (tid & 3) * 8;

    int grow = m0 + arow;
    const __half* aptr;
    if (MODE == 0) {
        aptr = A + (size_t)grow*Kdim + acw*2;
    } else {
        int bq = grow / L, tq = grow - bq*L;
        aptr = A + ((size_t)(bq*NB + n)*L + tq)*Kdim + acw*2;
    }
    const __half* wptr = W + (size_t)(nt*64 + brow)*Kdim + bcw*2;
    uint32_t* Ad = gsw + arow*GW_STRIDE + acw;
    uint32_t* Bd = gsw + GA_TILEW + brow*GW_STRIDE + bcw;

    int wid = tid >> 5, lane = tid & 31;
    int g = lane >> 2, t = lane & 3;
    int warp_m = (wid >> 2) * 64, warp_n = (wid & 3) * 16;

    float acc[4][2][4];
    #pragma unroll
    for (int mi = 0; mi < 4; mi++)
        #pragma unroll
        for (int ni = 0; ni < 2; ni++)
            #pragma unroll
            for (int r = 0; r < 4; r++) acc[mi][ni][r] = 0.f;

    int NS = Kdim >> 6;

    #pragma unroll
    for (int j = 0; j < 4; j++) cp_async16(Ad + j*4, aptr + j*8);
    #pragma unroll
    for (int j = 0; j < 2; j++) cp_async16(Bd + j*4, wptr + j*8);
    CP_COMMIT();

    for (int s = 0; s < NS; s++) {
        CP_WAIT0();
        __syncthreads();

        if (s + 1 < NS) {
            int nb = (s+1) & 1;
            int ko = (s+1) * 64;   // halves
            #pragma unroll
            for (int j = 0; j < 4; j++)
                cp_async16(Ad + nb*GSTAGEW + j*4, aptr + ko + j*8);
            #pragma unroll
            for (int j = 0; j < 2; j++)
                cp_async16(Bd + nb*GSTAGEW + j*4, wptr + ko + j*8);
            CP_COMMIT();
        }

        const uint32_t* Ab = gsw + (s & 1)*GSTAGEW;
        const uint32_t* Bb = Ab + GA_TILEW;
        #pragma unroll
        for (int k0w = 0; k0w < 32; k0w += 8) {
            // dual k-permutation at word level: physical words (2t,2t+1) feed
            // k-slot words (t, t+4) in BOTH operands -> dot product unchanged.
            uint2 afa[4], afb[4], bf[2];
            #pragma unroll
            for (int mi = 0; mi < 4; mi++) {
                int r0 = warp_m + mi*16 + g;
                afa[mi] = *(const uint2*)&Ab[r0*GW_STRIDE     + k0w + 2*t];
                afb[mi] = *(const uint2*)&Ab[(r0+8)*GW_STRIDE + k0w + 2*t];
            }
            #pragma unroll
            for (int ni = 0; ni < 2; ni++) {
                int c = warp_n + ni*8 + g;
                bf[ni] = *(const uint2*)&Bb[c*GW_STRIDE + k0w + 2*t];
            }
            #pragma unroll
            for (int mi = 0; mi < 4; mi++)
                #pragma unroll
                for (int ni = 0; ni < 2; ni++)
                    mma_f16(acc[mi][ni][0], acc[mi][ni][1],
                            acc[mi][ni][2], acc[mi][ni][3],
                            afa[mi].x, afb[mi].x, afa[mi].y, afb[mi].y,
                            bf[ni].x, bf[ni].y);
        }
    }

    // epilogue
    #pragma unroll
    for (int mi = 0; mi < 4; mi++) {
        #pragma unroll
        for (int ni = 0; ni < 2; ni++) {
            int col = nt*64 + warp_n + ni*8 + t*2;
            float2 bv = *(const float2*)(bias + col);
            #pragma unroll
            for (int h2 = 0; h2 < 2; h2++) {
                int row = m0 + warp_m + mi*16 + g + h2*8;
                float ox = (acc[mi][ni][h2*2+0] + bv.x) * oscale;
                float oy = (acc[mi][ni][h2*2+1] + bv.y) * oscale;
                if (MODE == 0) {
                    int bq = row / L; int l = row - bq*L;
                    int hh = col >> 6; int hd = col & 63;
                    size_t idx = (((size_t)(bq*Hh + hh))*((size_t)NB*L)
                                  + (size_t)n*L + l)*HDc + hd;
                    *(uint32_t*)((__half*)C + idx) = pack16(ox, oy);
                } else {
                    float2 o; o.x = ox; o.y = oy;
                    *(float2*)((float*)C + ((size_t)n*(Bc*Tt) + row)*Dd + col) = o;
                }
            }
        }
    }
}

// merged Q + K + V projections: grid (16, 16, 9), tile 128x64
__global__ __launch_bounds__(256, 3) void gemm_qkv_kernel(
    const __half* __restrict__ xn, const __half* __restrict__ xfn,
    const __half* __restrict__ qw, const float* __restrict__ qb,
    const __half* __restrict__ kw, const float* __restrict__ kb,
    const __half* __restrict__ vw, const float* __restrict__ vb,
    __half* __restrict__ Qp, __half* __restrict__ Kp, __half* __restrict__ Vp)
{
    int z = blockIdx.z;
    int mt = blockIdx.x, nt = blockIdx.y;
    if (z < 3) {
        int n = z;
        gemm_body<0>(xn + (size_t)n*(Bc*Tt)*Dd, qw + (size_t)n*Dd*Dd,
                     qb + n*Dd, Qp, Dd, Tt, n, mt, nt, 0.125f); // fold 1/sqrt(64)
    } else {
        if (mt >= 8) return;
        int zz = z - 3;
        int n = (zz < 3) ? zz : zz - 3;
        const __half* W = (zz < 3) ? kw + (size_t)n*Dd*DXFc : vw + (size_t)n*Dd*DXFc;
        const float* bb = (zz < 3) ? kb + n*Dd : vb + n*Dd;
        __half* C       = (zz < 3) ? Kp : Vp;
        gemm_body<0>(xfn + (size_t)n*(Bc*Nf)*DXFc, W, bb, C, DXFc, Nf, n, mt, nt, 1.0f);
    }
}

// output projection: grid (16, 16, 3), tile 128x64
__global__ __launch_bounds__(256, 3) void gemm_out_kernel(
    const __half* __restrict__ att, const __half* __restrict__ ow,
    const float* __restrict__ ob, float* __restrict__ out)
{
    int n = blockIdx.z;
    gemm_body<1>(att, ow + (size_t)n*Dd*Dd, ob + n*Dd, out,
                 Dd, Tt, n, blockIdx.x, blockIdx.y, 1.0f);
}

// ---------------- kernel 4: fp16 flash attention ----------------
#define AT_STRIDE 40
#define AT_QS 0
#define AT_KS (128*AT_STRIDE)                 // 5120
#define AT_VT (AT_KS + 64*AT_STRIDE)          // 7680
#define AT_PS (AT_VT + 64*AT_STRIDE)          // 10240
#define ATTN_SMEM ((AT_PS + 128*AT_STRIDE)*4) // 61440 bytes
__global__ __launch_bounds__(256, 2) void attn_f16_kernel(
    const __half* __restrict__ Q, const __half* __restrict__ K,
    const __half* __restrict__ V, __half* __restrict__ O)
{
    extern __shared__ uint32_t sh[];
    uint32_t* Qs = sh + AT_QS;
    uint32_t* Ks = sh + AT_KS;
    uint32_t* Vt = sh + AT_VT;
    uint32_t* Ps = sh + AT_PS;

    int qt = blockIdx.x, bh = blockIdx.y;
    int tid = threadIdx.x;
    int wid = tid >> 5, lane = tid & 31;
    int g = lane >> 2, t = lane & 3;
    int r0 = wid*16 + g, r1 = r0 + 8;

    {
        int lrow = tid >> 1, lw = (tid & 1) * 16;
        const uint4* src = (const uint4*)(Q + ((size_t)bh*SQ + qt*128 + lrow)*HDc + lw*2);
        uint32_t* dst = Qs + lrow*AT_STRIDE + lw;
        #pragma unroll
        for (int j = 0; j < 4; j++) {
            uint4 v = src[j];
            *(uint4*)(dst + j*4) = v;
        }
    }

    float m0 = -3.0e38f, m1 = -3.0e38f, l0 = 0.f, l1 = 0.f;
    float acc[8][4];
    #pragma unroll
    for (int ni = 0; ni < 8; ni++)
        #pragma unroll
        for (int r = 0; r < 4; r++) acc[ni][r] = 0.f;

    for (int kt = 0; kt < SKk/64; kt++) {
        {
            int lrow = tid >> 2, lw = (tid & 3) * 8;
            const uint4* kp = (const uint4*)(K + ((size_t)bh*SKk + kt*64 + lrow)*HDc + lw*2);
            uint32_t* kd = Ks + lrow*AT_STRIDE + lw;
            *(uint4*)(kd)     = kp[0];
            *(uint4*)(kd + 4) = kp[1];
        }
        {
            int jp = tid & 31;
            int dg = tid >> 5;
            const __half* vrow = V + ((size_t)bh*SKk + kt*64 + 2*jp)*HDc + dg*8;
            uint4 va = *(const uint4*)(vrow);
            uint4 vb = *(const uint4*)(vrow + HDc);
            const uint32_t* pa = (const uint32_t*)&va;
            const uint32_t* pb = (const uint32_t*)&vb;
            #pragma unroll
            for (int i = 0; i < 8; i++) {
                uint32_t w = __byte_perm(pa[i>>1], pb[i>>1], (i & 1) ? 0x7632 : 0x5410);
                Vt[(dg*8 + i)*AT_STRIDE + jp] = w;
            }
        }
        __syncthreads();

        float sf[8][4];
        #pragma unroll
        for (int ni = 0; ni < 8; ni++)
            #pragma unroll
            for (int r = 0; r < 4; r++) sf[ni][r] = 0.f;

        #pragma unroll
        for (int k0w = 0; k0w < 32; k0w += 8) {
            uint2 aA = *(const uint2*)&Qs[r0*AT_STRIDE + k0w + 2*t];
            uint2 aB = *(const uint2*)&Qs[r1*AT_STRIDE + k0w + 2*t];
            #pragma unroll
            for (int ni = 0; ni < 8; ni++) {
                uint2 b = *(const uint2*)&Ks[(ni*8+g)*AT_STRIDE + k0w + 2*t];
                mma_f16(sf[ni][0], sf[ni][1], sf[ni][2], sf[ni][3],
                        aA.x, aB.x, aA.y, aB.y, b.x, b.y);
            }
        }

        float mx0 = -3.0e38f, mx1 = -3.0e38f;
        #pragma unroll
        for (int ni = 0; ni < 8; ni++) {
            mx0 = fmaxf(mx0, fmaxf(sf[ni][0], sf[ni][1]));
            mx1 = fmaxf(mx1, fmaxf(sf[ni][2], sf[ni][3]));
        }
        mx0 = fmaxf(mx0, __shfl_xor_sync(0xffffffffu, mx0, 1));
        mx0 = fmaxf(mx0, __shfl_xor_sync(0xffffffffu, mx0, 2));
        mx1 = fmaxf(mx1, __shfl_xor_sync(0xffffffffu, mx1, 1));
        mx1 = fmaxf(mx1, __shfl_xor_sync(0xffffffffu, mx1, 2));
        float mn0 = fmaxf(m0, mx0), mn1 = fmaxf(m1, mx1);
        float rs0 = __expf(m0 - mn0), rs1 = __expf(m1 - mn1);
        float ls0 = 0.f, ls1 = 0.f;
        #pragma unroll
        for (int ni = 0; ni < 8; ni++) {
            sf[ni][0] = __expf(sf[ni][0] - mn0);
            sf[ni][1] = __expf(sf[ni][1] - mn0);
            sf[ni][2] = __expf(sf[ni][2] - mn1);
            sf[ni][3] = __expf(sf[ni][3] - mn1);
            ls0 += sf[ni][0] + sf[ni][1];
            ls1 += sf[ni][2] + sf[ni][3];
        }
        ls0 += __shfl_xor_sync(0xffffffffu, ls0, 1);
        ls0 += __shfl_xor_sync(0xffffffffu, ls0, 2);
        ls1 += __shfl_xor_sync(0xffffffffu, ls1, 1);
        ls1 += __shfl_xor_sync(0xffffffffu, ls1, 2);
        l0 = l0*rs0 + ls0;  m0 = mn0;
        l1 = l1*rs1 + ls1;  m1 = mn1;
        #pragma unroll
        for (int ni = 0; ni < 8; ni++) {
            acc[ni][0] *= rs0; acc[ni][1] *= rs0;
            acc[ni][2] *= rs1; acc[ni][3] *= rs1;
        }

        #pragma unroll
        for (int ni = 0; ni < 8; ni++) {
            Ps[r0*AT_STRIDE + ni*4 + t] = pack16(sf[ni][0], sf[ni][1]);
            Ps[r1*AT_STRIDE + ni*4 + t] = pack16(sf[ni][2], sf[ni][3]);
        }
        __syncwarp();

        #pragma unroll
        for (int k0w = 0; k0w < 32; k0w += 8) {
            uint2 aA = *(const uint2*)&Ps[r0*AT_STRIDE + k0w + 2*t];
            uint2 aB = *(const uint2*)&Ps[r1*AT_STRIDE + k0w + 2*t];
            #pragma unroll
            for (int ni = 0; ni < 8; ni++) {
                uint2 b = *(const uint2*)&Vt[(ni*8+g)*AT_STRIDE + k0w + 2*t];
                mma_f16(acc[ni][0], acc[ni][1], acc[ni][2], acc[ni][3],
                        aA.x, aB.x, aA.y, aB.y, b.x, b.y);
            }
        }
        __syncthreads();
    }

    float inv0 = 1.f / l0, inv1 = 1.f / l1;
    int b = bh >> 4, h = bh & 15;
    int q0 = qt*128 + r0, q1 = q0 + 8;
    __half* O0 = O + ((size_t)b*SQ + q0)*Dd + h*64;
    __half* O1 = O + ((size_t)b*SQ + q1)*Dd + h*64;
    #pragma unroll
    for (int ni = 0; ni < 8; ni++) {
        int col = ni*8 + 2*t;
        *(uint32_t*)(O0 + col) = pack16(acc[ni][0]*inv0, acc[ni][1]*inv0);
        *(uint32_t*)(O1 + col) = pack16(acc[ni][2]*inv1, acc[ni][3]*inv1);
    }
}

// ---------------- launch ----------------
extern "C" void kernel_launch(void* const* d_in, const int* in_sizes, int n_in,
                              void* d_out, int out_size)
{
    const float* x1   = (const float*)d_in[0];
    const float* x2   = (const float*)d_in[1];
    const float* x3   = (const float*)d_in[2];
    const float* xf1  = (const float*)d_in[3];
    const float* xf2  = (const float*)d_in[4];
    const float* xf3  = (const float*)d_in[5];
    const float* emb  = (const float*)d_in[6];
    const float* axw  = (const float*)d_in[7];
    const float* axb  = (const float*)d_in[8];
    const float* afw  = (const float*)d_in[9];
    const float* afb  = (const float*)d_in[10];
    const float* q_w  = (const float*)d_in[11];
    const float* q_b  = (const float*)d_in[12];
    const float* k_w  = (const float*)d_in[13];
    const float* k_b  = (const float*)d_in[14];
    const float* v_w  = (const float*)d_in[15];
    const float* v_b  = (const float*)d_in[16];
    const float* o_w  = (const float*)d_in[17];
    const float* o_b  = (const float*)d_in[18];
    float* out = (float*)d_out;

    float *mx, *mxf;
    __half *xn, *xfn, *Qp, *Kp, *Vp, *att, *qw, *kw, *vw, *ow;
    cudaGetSymbolAddress((void**)&mx,  g_mod_x);
    cudaGetSymbolAddress((void**)&mxf, g_mod_xf);
    cudaGetSymbolAddress((void**)&xn,  g_xn);
    cudaGetSymbolAddress((void**)&xfn, g_xfn);
    cudaGetSymbolAddress((void**)&Qp,  g_Qh);
    cudaGetSymbolAddress((void**)&Kp,  g_Kh);
    cudaGetSymbolAddress((void**)&Vp,  g_Vh);
    cudaGetSymbolAddress((void**)&att, g_att);
    cudaGetSymbolAddress((void**)&qw,  g_qw);
    cudaGetSymbolAddress((void**)&kw,  g_kw);
    cudaGetSymbolAddress((void**)&vw,  g_vw);
    cudaGetSymbolAddress((void**)&ow,  g_ow);

    cudaFuncSetAttribute(attn_f16_kernel,
        cudaFuncAttributeMaxDynamicSharedMemorySize, ATTN_SMEM);
    cudaFuncSetAttribute(gemm_qkv_kernel,
        cudaFuncAttributeMaxDynamicSharedMemorySize, GEMM_SMEM);
    cudaFuncSetAttribute(gemm_out_kernel,
        cudaFuncAttributeMaxDynamicSharedMemorySize, GEMM_SMEM);

    // 1: weight conversion to fp16
    cvt_w_kernel<<<dim3(NB*Dd*Dd/1024, 4), 256>>>(
        q_w, k_w, v_w, o_w, qw, kw, vw, ow);

    // 2: adaLN modulation (both sets)
    adaln_mod_kernel<<<dim3(8, Bc, 2*NB), 256>>>(
        emb, axw, axb, afw, afb, mx, mxf);

    // 3: LayerNorm + modulate (both sets)
    ln_mod_kernel<<<NB*Bc*Tt + NB*Bc*Nf, 256>>>(
        x1, x2, x3, xf1, xf2, xf3, mx, mxf, xn, xfn);

    // 4: merged Q/K/V projections (tile 128x64, 3 CTAs/SM)
    gemm_qkv_kernel<<<dim3(16, 16, 9), 256, GEMM_SMEM>>>(
        xn, xfn, qw, q_b, kw, k_b, vw, v_b, Qp, Kp, Vp);

    // 5: attention (fp16 MMA)
    attn_f16_kernel<<<dim3(SQ/128, BHc), 256, ATTN_SMEM>>>(Qp, Kp, Vp, att);

    // 6: output projection (tile 128x64, 3 CTAs/SM, fp32 out)
    gemm_out_kernel<<<dim3(16, 16, 3), 256, GEMM_SMEM>>>(att, ow, o_b, out);
}

// round 15
// speedup vs baseline: 1.0816x; 1.0816x over previous
#include <cuda_runtime.h>
#include <cuda_fp16.h>
#include <math.h>
#include <stdint.h>

// ---------------- problem constants ----------------
#define NB   3
#define Bc   4
#define Tt   512
#define Nf   256
#define Dd   1024
#define DXFc 512
#define Ee   1024
#define Hh   16
#define HDc  64
#define SQ   (NB*Tt)   // 1536
#define SKk  (NB*Nf)   // 768
#define BHc  (Bc*Hh)   // 64
#define EPSV 1e-6f

// ---------------- scratch (fp16 activations/weights) ----------------
__device__ float g_mod_x [NB*Bc*2*Dd];
__device__ float g_mod_xf[NB*Bc*2*DXFc];
__device__ __align__(16) __half g_xn [NB*Bc*Tt*Dd];
__device__ __align__(16) __half g_xfn[NB*Bc*Nf*DXFc];
__device__ __align__(16) __half g_Qh[(size_t)BHc*SQ*HDc];
__device__ __align__(16) __half g_Kh[(size_t)BHc*SKk*HDc];
__device__ __align__(16) __half g_Vh[(size_t)BHc*SKk*HDc];
__device__ __align__(16) __half g_att[(size_t)Bc*SQ*Dd];
__device__ __align__(16) __half g_qw[NB*Dd*Dd];
__device__ __align__(16) __half g_kw[NB*Dd*DXFc];
__device__ __align__(16) __half g_vw[NB*Dd*DXFc];
__device__ __align__(16) __half g_ow[NB*Dd*Dd];

// ---------------- helpers ----------------
__device__ __forceinline__ uint32_t pack16(float lo, float hi) {
    uint32_t r;
    asm("cvt.rn.f16x2.f32 %0, %1, %2;" : "=r"(r) : "f"(hi), "f"(lo));
    return r;
}
__device__ __forceinline__ void mma_f16(
    float& d0, float& d1, float& d2, float& d3,
    uint32_t a0, uint32_t a1, uint32_t a2, uint32_t a3,
    uint32_t b0, uint32_t b1)
{
    asm volatile(
        "mma.sync.aligned.m16n8k16.row.col.f32.f16.f16.f32 "
        "{%0,%1,%2,%3}, {%4,%5,%6,%7}, {%8,%9}, {%0,%1,%2,%3};"
        : "+f"(d0), "+f"(d1), "+f"(d2), "+f"(d3)
        : "r"(a0), "r"(a1), "r"(a2), "r"(a3), "r"(b0), "r"(b1));
}
__device__ __forceinline__ void ldsm_x4(
    uint32_t& r0, uint32_t& r1, uint32_t& r2, uint32_t& r3, uint32_t addr)
{
    asm volatile(
        "ldmatrix.sync.aligned.m8n8.x4.shared.b16 {%0,%1,%2,%3}, [%4];"
        : "=r"(r0), "=r"(r1), "=r"(r2), "=r"(r3) : "r"(addr));
}
__device__ __forceinline__ void cp_async16(void* dst, const void* src) {
    uint32_t s = (uint32_t)__cvta_generic_to_shared(dst);
    asm volatile("cp.async.cg.shared.global [%0], [%1], 16;" :: "r"(s), "l"(src));
}
#define CP_COMMIT() asm volatile("cp.async.commit_group;")
#define CP_WAIT0()  asm volatile("cp.async.wait_group 0;" ::: "memory")

// ---------------- kernel 0: convert ALL weights to fp16 ----------------
__global__ __launch_bounds__(256) void cvt_w_kernel(
    const float* __restrict__ qs, const float* __restrict__ ks,
    const float* __restrict__ vs, const float* __restrict__ os,
    __half* __restrict__ qd, __half* __restrict__ kd,
    __half* __restrict__ vd, __half* __restrict__ od)
{
    int y = blockIdx.y;
    const float* src; __half* dst; int n4;
    if (y == 0)      { src = qs; dst = qd; n4 = NB*Dd*Dd/4; }
    else if (y == 1) { src = ks; dst = kd; n4 = NB*Dd*DXFc/4; }
    else if (y == 2) { src = vs; dst = vd; n4 = NB*Dd*DXFc/4; }
    else             { src = os; dst = od; n4 = NB*Dd*Dd/4; }
    int i = blockIdx.x*256 + threadIdx.x;
    if (i < n4) {
        float4 v = ((const float4*)src)[i];
        uint2 o;
        o.x = pack16(v.x, v.y);
        o.y = pack16(v.z, v.w);
        ((uint2*)dst)[i] = o;
    }
}

// ---------------- kernel 1: adaLN modulation (both sets, one launch) ----------------
__global__ __launch_bounds__(256) void adaln_mod_kernel(
    const float* __restrict__ emb,
    const float* __restrict__ wx,  const float* __restrict__ bx,
    const float* __restrict__ wxf, const float* __restrict__ bxf,
    float* __restrict__ outx, float* __restrict__ outxf)
{
    int z = blockIdx.z;
    int isx = (z < NB);
    int n = isx ? z : z - NB;
    int twoD = isx ? 2*Dd : 2*DXFc;
    int j = blockIdx.x*256 + threadIdx.x;
    if (j >= twoD) return;
    const float* w    = isx ? wx   : wxf;
    const float* bvec = isx ? bx   : bxf;
    float* out        = isx ? outx : outxf;

    __shared__ float se[Ee];
    int b = blockIdx.y;
    int tid = threadIdx.x;
    for (int i = tid*4; i < Ee; i += 256*4) {
        float4 v = *(const float4*)(emb + (size_t)b*Ee + i);
        se[i+0] = v.x / (1.f + __expf(-v.x));
        se[i+1] = v.y / (1.f + __expf(-v.y));
        se[i+2] = v.z / (1.f + __expf(-v.z));
        se[i+3] = v.w / (1.f + __expf(-v.w));
    }
    __syncthreads();
    const float* wr = w + ((size_t)n*twoD + j)*Ee;
    float acc = 0.f;
    #pragma unroll 8
    for (int e = 0; e < Ee; e += 4) {
        float4 wv = *(const float4*)(wr + e);
        acc += se[e]*wv.x + se[e+1]*wv.y + se[e+2]*wv.z + se[e+3]*wv.w;
    }
    out[((size_t)n*Bc + b)*twoD + j] = acc + bvec[(size_t)n*twoD + j];
}

// ---------------- kernel 2: LayerNorm + modulate -> fp16 (both sets) ----------------
__global__ __launch_bounds__(256) void ln_mod_kernel(
    const float* __restrict__ x1, const float* __restrict__ x2,
    const float* __restrict__ x3,
    const float* __restrict__ xf1, const float* __restrict__ xf2,
    const float* __restrict__ xf3,
    const float* __restrict__ modx, const float* __restrict__ modxf,
    __half* __restrict__ xn, __half* __restrict__ xfn)
{
    int r = blockIdx.x;
    int dim, n, b;
    const float* xp;
    const float* mod;
    __half* op;
    if (r < NB*Bc*Tt) {
        dim = Dd;
        n = r / (Bc*Tt);
        int rr = r - n*(Bc*Tt);
        b = rr / Tt;
        xp = (n == 0 ? x1 : (n == 1 ? x2 : x3)) + (size_t)rr*dim;
        mod = modx + ((size_t)n*Bc + b)*2*dim;
        op = xn + (size_t)r*dim;
    } else {
        int r2 = r - NB*Bc*Tt;
        dim = DXFc;
        n = r2 / (Bc*Nf);
        int rr = r2 - n*(Bc*Nf);
        b = rr / Nf;
        xp = (n == 0 ? xf1 : (n == 1 ? xf2 : xf3)) + (size_t)rr*dim;
        mod = modxf + ((size_t)n*Bc + b)*2*dim;
        op = xfn + (size_t)r2*dim;
    }
    int tid = threadIdx.x;

    float s1 = 0.f, s2 = 0.f;
    for (int d = tid*4; d < dim; d += 1024) {
        float4 v = *(const float4*)(xp + d);
        s1 += v.x + v.y + v.z + v.w;
        s2 += v.x*v.x + v.y*v.y + v.z*v.z + v.w*v.w;
    }
    #pragma unroll
    for (int off = 16; off; off >>= 1) {
        s1 += __shfl_xor_sync(0xffffffffu, s1, off);
        s2 += __shfl_xor_sync(0xffffffffu, s2, off);
    }
    __shared__ float rs1[8], rs2[8];
    int wid = tid >> 5, lane = tid & 31;
    if (!lane) { rs1[wid] = s1; rs2[wid] = s2; }
    __syncthreads();
    s1 = rs1[0]+rs1[1]+rs1[2]+rs1[3]+rs1[4]+rs1[5]+rs1[6]+rs1[7];
    s2 = rs2[0]+rs2[1]+rs2[2]+rs2[3]+rs2[4]+rs2[5]+rs2[6]+rs2[7];

    float inv = 1.f / (float)dim;
    float mu  = s1 * inv;
    float var = s2 * inv - mu*mu;
    float rstd = rsqrtf(var + EPSV);

    const float* sc = mod;
    const float* sh = mod + dim;
    for (int d = tid*4; d < dim; d += 1024) {
        float4 v = *(const float4*)(xp + d);
        float4 s = *(const float4*)(sc + d);
        float4 h = *(const float4*)(sh + d);
        uint2 o;
        o.x = pack16((v.x - mu)*rstd*(1.f + s.x) + h.x,
                     (v.y - mu)*rstd*(1.f + s.y) + h.y);
        o.y = pack16((v.z - mu)*rstd*(1.f + s.z) + h.z,
                     (v.w - mu)*rstd*(1.f + s.w) + h.w);
        *(uint2*)(op + d) = o;
    }
}

// ---------------- kernel 3: fp16 GEMM with ldmatrix fragment loads ----------------
// 256 thr, 2 CTAs/SM. Tile TM x 128 (TM = 128 or 64), k-slab 64 halves, 2-stage cp.async.
// 8 warps in 2x4 grid; warp tile (TM/2) x 32. Fragments via ldmatrix.x4 (standard layout).
#define GW_STRIDE 36                 // words per smem row (32 + 4 pad; ldmatrix conflict-free)

// MODE 0: A rows [M][K] fp16 (pre-offset to block n); C = fp16 head-layout, scaled.
// MODE 1: A = g_att rows (bq*NB+n)*L+tq fp16; C = fp32 [n][Bc*Tt][Dd] (d_out).
template<int MODE, int TM>
__device__ __forceinline__ void gemm_body(
    const __half* __restrict__ A, const __half* __restrict__ W,
    const float* __restrict__ bias, void* __restrict__ C,
    int Kdim, int L, int n, int mt, int nt, float oscale)
{
    constexpr int ATILEW = TM*GW_STRIDE;
    constexpr int BTILEW = 128*GW_STRIDE;
    constexpr int STAGEW = ATILEW + BTILEW;
    constexpr int MI = TM/32;

    extern __shared__ uint32_t gsw[];
    int tid = threadIdx.x;
    int m0 = mt*TM;

    // loaders
    constexpr int AJ = (TM == 128) ? 4 : 2;
    int arow, acw;
    if (TM == 128) { arow = tid >> 1; acw = (tid & 1) * 16; }
    else           { arow = tid >> 2; acw = (tid & 3) * 8;  }
    int brow = tid >> 1, bcw = (tid & 1) * 16;

    int grow = m0 + arow;
    const __half* aptr;
    if (MODE == 0) {
        aptr = A + (size_t)grow*Kdim + acw*2;
    } else {
        int bq = grow / L, tq = grow - bq*L;
        aptr = A + ((size_t)(bq*NB + n)*L + tq)*Kdim + acw*2;
    }
    const __half* wptr = W + (size_t)(nt*128 + brow)*Kdim + bcw*2;
    uint32_t* Ad = gsw + arow*GW_STRIDE + acw;
    uint32_t* Bd = gsw + ATILEW + brow*GW_STRIDE + bcw;

    int wid = tid >> 5, lane = tid & 31;
    int g = lane >> 2, t = lane & 3;
    int warp_m = (wid >> 2) * (TM/2), warp_n = (wid & 3) * 32;

    // ldmatrix lane addressing (byte offsets)
    uint32_t smem_base = (uint32_t)__cvta_generic_to_shared(gsw);
    int row_local = lane & 15;          // A: tile row within 16
    int ksel_a = lane >> 4;             // A: 0 = k halves 0-7, 1 = 8-15
    uint32_t a_off = (uint32_t)(warp_m + row_local)*(GW_STRIDE*4) + ksel_a*16;
    int col_local = (lane & 7) + ((lane >> 4) << 3);  // B: col within 16-group
    int ksel_b = (lane >> 3) & 1;
    uint32_t b_off = (uint32_t)ATILEW*4
                   + (uint32_t)(warp_n + col_local)*(GW_STRIDE*4) + ksel_b*16;

    float acc[MI][4][4];
    #pragma unroll
    for (int mi = 0; mi < MI; mi++)
        #pragma unroll
        for (int ni = 0; ni < 4; ni++)
            #pragma unroll
            for (int r = 0; r < 4; r++) acc[mi][ni][r] = 0.f;

    int NS = Kdim >> 6;

    #pragma unroll
    for (int j = 0; j < AJ; j++) cp_async16(Ad + j*4, aptr + j*8);
    #pragma unroll
    for (int j = 0; j < 4; j++)  cp_async16(Bd + j*4, wptr + j*8);
    CP_COMMIT();

    for (int s = 0; s < NS; s++) {
        CP_WAIT0();
        __syncthreads();

        if (s + 1 < NS) {
            int nb = (s+1) & 1;
            int ko = (s+1) * 64;   // halves
            #pragma unroll
            for (int j = 0; j < AJ; j++)
                cp_async16(Ad + nb*STAGEW + j*4, aptr + ko + j*8);
            #pragma unroll
            for (int j = 0; j < 4; j++)
                cp_async16(Bd + nb*STAGEW + j*4, wptr + ko + j*8);
            CP_COMMIT();
        }

        uint32_t sb = smem_base + (uint32_t)((s & 1)*STAGEW)*4;
        #pragma unroll
        for (int ks = 0; ks < 4; ks++) {          // k = 16 halves per step
            uint32_t af[MI][4], bf[2][4];
            #pragma unroll
            for (int mi = 0; mi < MI; mi++)
                ldsm_x4(af[mi][0], af[mi][1], af[mi][2], af[mi][3],
                        sb + a_off + (uint32_t)(mi*16*GW_STRIDE*4) + ks*32);
            #pragma unroll
            for (int p = 0; p < 2; p++)
                ldsm_x4(bf[p][0], bf[p][1], bf[p][2], bf[p][3],
                        sb + b_off + (uint32_t)(p*16*GW_STRIDE*4) + ks*32);
            #pragma unroll
            for (int mi = 0; mi < MI; mi++)
                #pragma unroll
                for (int ni = 0; ni < 4; ni++) {
                    int p = ni >> 1, q = ni & 1;
                    mma_f16(acc[mi][ni][0], acc[mi][ni][1],
                            acc[mi][ni][2], acc[mi][ni][3],
                            af[mi][0], af[mi][1], af[mi][2], af[mi][3],
                            bf[p][q*2], bf[p][q*2+1]);
                }
        }
    }

    // epilogue (C fragment layout unchanged: row = base+g(+8), cols 2t,2t+1)
    #pragma unroll
    for (int mi = 0; mi < MI; mi++) {
        #pragma unroll
        for (int ni = 0; ni < 4; ni++) {
            int col = nt*128 + warp_n + ni*8 + t*2;
            float2 bv = *(const float2*)(bias + col);
            #pragma unroll
            for (int h2 = 0; h2 < 2; h2++) {
                int row = m0 + warp_m + mi*16 + g + h2*8;
                float ox = (acc[mi][ni][h2*2+0] + bv.x) * oscale;
                float oy = (acc[mi][ni][h2*2+1] + bv.y) * oscale;
                if (MODE == 0) {
                    int bq = row / L; int l = row - bq*L;
                    int hh = col >> 6; int hd = col & 63;
                    size_t idx = (((size_t)(bq*Hh + hh))*((size_t)NB*L)
                                  + (size_t)n*L + l)*HDc + hd;
                    *(uint32_t*)((__half*)C + idx) = pack16(ox, oy);
                } else {
                    float2 o; o.x = ox; o.y = oy;
                    *(float2*)((float*)C + ((size_t)n*(Bc*Tt) + row)*Dd + col) = o;
                }
            }
        }
    }
}

#define GEMM_SMEM_128 (2*(128*GW_STRIDE + 128*GW_STRIDE)*4)   // 73728
#define GEMM_SMEM_64  (2*(64*GW_STRIDE  + 128*GW_STRIDE)*4)   // 55296

// merged Q + K + V projections: grid (16, 8, 9), tile 128x128
__global__ __launch_bounds__(256, 2) void gemm_qkv_kernel(
    const __half* __restrict__ xn, const __half* __restrict__ xfn,
    const __half* __restrict__ qw, const float* __restrict__ qb,
    const __half* __restrict__ kw, const float* __restrict__ kb,
    const __half* __restrict__ vw, const float* __restrict__ vb,
    __half* __restrict__ Qp, __half* __restrict__ Kp, __half* __restrict__ Vp)
{
    int z = blockIdx.z;
    int mt = blockIdx.x, nt = blockIdx.y;
    if (z < 3) {
        int n = z;
        gemm_body<0,128>(xn + (size_t)n*(Bc*Tt)*Dd, qw + (size_t)n*Dd*Dd,
                         qb + n*Dd, Qp, Dd, Tt, n, mt, nt, 0.125f); // fold 1/sqrt(64)
    } else {
        if (mt >= 8) return;
        int zz = z - 3;
        int n = (zz < 3) ? zz : zz - 3;
        const __half* W = (zz < 3) ? kw + (size_t)n*Dd*DXFc : vw + (size_t)n*Dd*DXFc;
        const float* bb = (zz < 3) ? kb + n*Dd : vb + n*Dd;
        __half* C       = (zz < 3) ? Kp : Vp;
        gemm_body<0,128>(xfn + (size_t)n*(Bc*Nf)*DXFc, W, bb, C, DXFc, Nf, n, mt, nt, 1.0f);
    }
}

// output projection: grid (32, 8, 3), tile 64x128 (wave-quantization fix)
__global__ __launch_bounds__(256, 2) void gemm_out_kernel(
    const __half* __restrict__ att, const __half* __restrict__ ow,
    const float* __restrict__ ob, float* __restrict__ out)
{
    int n = blockIdx.z;
    gemm_body<1,64>(att, ow + (size_t)n*Dd*Dd, ob + n*Dd, out,
                    Dd, Tt, n, blockIdx.x, blockIdx.y, 1.0f);
}

// ---------------- kernel 4: fp16 flash attention (r12, unchanged) ----------------
#define AT_STRIDE 40
#define AT_QS 0
#define AT_KS (128*AT_STRIDE)                 // 5120
#define AT_VT (AT_KS + 64*AT_STRIDE)          // 7680
#define AT_PS (AT_VT + 64*AT_STRIDE)          // 10240
#define ATTN_SMEM ((AT_PS + 128*AT_STRIDE)*4) // 61440 bytes
__global__ __launch_bounds__(256, 2) void attn_f16_kernel(
    const __half* __restrict__ Q, const __half* __restrict__ K,
    const __half* __restrict__ V, __half* __restrict__ O)
{
    extern __shared__ uint32_t sh[];
    uint32_t* Qs = sh + AT_QS;
    uint32_t* Ks = sh + AT_KS;
    uint32_t* Vt = sh + AT_VT;
    uint32_t* Ps = sh + AT_PS;

    int qt = blockIdx.x, bh = blockIdx.y;
    int tid = threadIdx.x;
    int wid = tid >> 5, lane = tid & 31;
    int g = lane >> 2, t = lane & 3;
    int r0 = wid*16 + g, r1 = r0 + 8;

    {
        int lrow = tid >> 1, lw = (tid & 1) * 16;
        const uint4* src = (const uint4*)(Q + ((size_t)bh*SQ + qt*128 + lrow)*HDc + lw*2);
        uint32_t* dst = Qs + lrow*AT_STRIDE + lw;
        #pragma unroll
        for (int j = 0; j < 4; j++) {
            uint4 v = src[j];
            *(uint4*)(dst + j*4) = v;
        }
    }

    float m0 = -3.0e38f, m1 = -3.0e38f, l0 = 0.f, l1 = 0.f;
    float acc[8][4];
    #pragma unroll
    for (int ni = 0; ni < 8; ni++)
        #pragma unroll
        for (int r = 0; r < 4; r++) acc[ni][r] = 0.f;

    for (int kt = 0; kt < SKk/64; kt++) {
        {
            int lrow = tid >> 2, lw = (tid & 3) * 8;
            const uint4* kp = (const uint4*)(K + ((size_t)bh*SKk + kt*64 + lrow)*HDc + lw*2);
            uint32_t* kd = Ks + lrow*AT_STRIDE + lw;
            *(uint4*)(kd)     = kp[0];
            *(uint4*)(kd + 4) = kp[1];
        }
        {
            int jp = tid & 31;
            int dg = tid >> 5;
            const __half* vrow = V + ((size_t)bh*SKk + kt*64 + 2*jp)*HDc + dg*8;
            uint4 va = *(const uint4*)(vrow);
            uint4 vb = *(const uint4*)(vrow + HDc);
            const uint32_t* pa = (const uint32_t*)&va;
            const uint32_t* pb = (const uint32_t*)&vb;
            #pragma unroll
            for (int i = 0; i < 8; i++) {
                uint32_t w = __byte_perm(pa[i>>1], pb[i>>1], (i & 1) ? 0x7632 : 0x5410);
                Vt[(dg*8 + i)*AT_STRIDE + jp] = w;
            }
        }
        __syncthreads();

        float sf[8][4];
        #pragma unroll
        for (int ni = 0; ni < 8; ni++)
            #pragma unroll
            for (int r = 0; r < 4; r++) sf[ni][r] = 0.f;

        #pragma unroll
        for (int k0w = 0; k0w < 32; k0w += 8) {
            uint2 aA = *(const uint2*)&Qs[r0*AT_STRIDE + k0w + 2*t];
            uint2 aB = *(const uint2*)&Qs[r1*AT_STRIDE + k0w + 2*t];
            #pragma unroll
            for (int ni = 0; ni < 8; ni++) {
                uint2 b = *(const uint2*)&Ks[(ni*8+g)*AT_STRIDE + k0w + 2*t];
                mma_f16(sf[ni][0], sf[ni][1], sf[ni][2], sf[ni][3],
                        aA.x, aB.x, aA.y, aB.y, b.x, b.y);
            }
        }

        float mx0 = -3.0e38f, mx1 = -3.0e38f;
        #pragma unroll
        for (int ni = 0; ni < 8; ni++) {
            mx0 = fmaxf(mx0, fmaxf(sf[ni][0], sf[ni][1]));
            mx1 = fmaxf(mx1, fmaxf(sf[ni][2], sf[ni][3]));
        }
        mx0 = fmaxf(mx0, __shfl_xor_sync(0xffffffffu, mx0, 1));
        mx0 = fmaxf(mx0, __shfl_xor_sync(0xffffffffu, mx0, 2));
        mx1 = fmaxf(mx1, __shfl_xor_sync(0xffffffffu, mx1, 1));
        mx1 = fmaxf(mx1, __shfl_xor_sync(0xffffffffu, mx1, 2));
        float mn0 = fmaxf(m0, mx0), mn1 = fmaxf(m1, mx1);
        float rs0 = __expf(m0 - mn0), rs1 = __expf(m1 - mn1);
        float ls0 = 0.f, ls1 = 0.f;
        #pragma unroll
        for (int ni = 0; ni < 8; ni++) {
            sf[ni][0] = __expf(sf[ni][0] - mn0);
            sf[ni][1] = __expf(sf[ni][1] - mn0);
            sf[ni][2] = __expf(sf[ni][2] - mn1);
            sf[ni][3] = __expf(sf[ni][3] - mn1);
            ls0 += sf[ni][0] + sf[ni][1];
            ls1 += sf[ni][2] + sf[ni][3];
        }
        ls0 += __shfl_xor_sync(0xffffffffu, ls0, 1);
        ls0 += __shfl_xor_sync(0xffffffffu, ls0, 2);
        ls1 += __shfl_xor_sync(0xffffffffu, ls1, 1);
        ls1 += __shfl_xor_sync(0xffffffffu, ls1, 2);
        l0 = l0*rs0 + ls0;  m0 = mn0;
        l1 = l1*rs1 + ls1;  m1 = mn1;
        #pragma unroll
        for (int ni = 0; ni < 8; ni++) {
            acc[ni][0] *= rs0; acc[ni][1] *= rs0;
            acc[ni][2] *= rs1; acc[ni][3] *= rs1;
        }

        #pragma unroll
        for (int ni = 0; ni < 8; ni++) {
            Ps[r0*AT_STRIDE + ni*4 + t] = pack16(sf[ni][0], sf[ni][1]);
            Ps[r1*AT_STRIDE + ni*4 + t] = pack16(sf[ni][2], sf[ni][3]);
        }
        __syncwarp();

        #pragma unroll
        for (int k0w = 0; k0w < 32; k0w += 8) {
            uint2 aA = *(const uint2*)&Ps[r0*AT_STRIDE + k0w + 2*t];
            uint2 aB = *(const uint2*)&Ps[r1*AT_STRIDE + k0w + 2*t];
            #pragma unroll
            for (int ni = 0; ni < 8; ni++) {
                uint2 b = *(const uint2*)&Vt[(ni*8+g)*AT_STRIDE + k0w + 2*t];
                mma_f16(acc[ni][0], acc[ni][1], acc[ni][2], acc[ni][3],
                        aA.x, aB.x, aA.y, aB.y, b.x, b.y);
            }
        }
        __syncthreads();
    }

    float inv0 = 1.f / l0, inv1 = 1.f / l1;
    int b = bh >> 4, h = bh & 15;
    int q0 = qt*128 + r0, q1 = q0 + 8;
    __half* O0 = O + ((size_t)b*SQ + q0)*Dd + h*64;
    __half* O1 = O + ((size_t)b*SQ + q1)*Dd + h*64;
    #pragma unroll
    for (int ni = 0; ni < 8; ni++) {
        int col = ni*8 + 2*t;
        *(uint32_t*)(O0 + col) = pack16(acc[ni][0]*inv0, acc[ni][1]*inv0);
        *(uint32_t*)(O1 + col) = pack16(acc[ni][2]*inv1, acc[ni][3]*inv1);
    }
}

// ---------------- launch ----------------
extern "C" void kernel_launch(void* const* d_in, const int* in_sizes, int n_in,
                              void* d_out, int out_size)
{
    const float* x1   = (const float*)d_in[0];
    const float* x2   = (const float*)d_in[1];
    const float* x3   = (const float*)d_in[2];
    const float* xf1  = (const float*)d_in[3];
    const float* xf2  = (const float*)d_in[4];
    const float* xf3  = (const float*)d_in[5];
    const float* emb  = (const float*)d_in[6];
    const float* axw  = (const float*)d_in[7];
    const float* axb  = (const float*)d_in[8];
    const float* afw  = (const float*)d_in[9];
    const float* afb  = (const float*)d_in[10];
    const float* q_w  = (const float*)d_in[11];
    const float* q_b  = (const float*)d_in[12];
    const float* k_w  = (const float*)d_in[13];
    const float* k_b  = (const float*)d_in[14];
    const float* v_w  = (const float*)d_in[15];
    const float* v_b  = (const float*)d_in[16];
    const float* o_w  = (const float*)d_in[17];
    const float* o_b  = (const float*)d_in[18];
    float* out = (float*)d_out;

    float *mx, *mxf;
    __half *xn, *xfn, *Qp, *Kp, *Vp, *att, *qw, *kw, *vw, *ow;
    cudaGetSymbolAddress((void**)&mx,  g_mod_x);
    cudaGetSymbolAddress((void**)&mxf, g_mod_xf);
    cudaGetSymbolAddress((void**)&xn,  g_xn);
    cudaGetSymbolAddress((void**)&xfn, g_xfn);
    cudaGetSymbolAddress((void**)&Qp,  g_Qh);
    cudaGetSymbolAddress((void**)&Kp,  g_Kh);
    cudaGetSymbolAddress((void**)&Vp,  g_Vh);
    cudaGetSymbolAddress((void**)&att, g_att);
    cudaGetSymbolAddress((void**)&qw,  g_qw);
    cudaGetSymbolAddress((void**)&kw,  g_kw);
    cudaGetSymbolAddress((void**)&vw,  g_vw);
    cudaGetSymbolAddress((void**)&ow,  g_ow);

    cudaFuncSetAttribute(attn_f16_kernel,
        cudaFuncAttributeMaxDynamicSharedMemorySize, ATTN_SMEM);
    cudaFuncSetAttribute(gemm_qkv_kernel,
        cudaFuncAttributeMaxDynamicSharedMemorySize, GEMM_SMEM_128);
    cudaFuncSetAttribute(gemm_out_kernel,
        cudaFuncAttributeMaxDynamicSharedMemorySize, GEMM_SMEM_64);

    // 1: weight conversion to fp16
    cvt_w_kernel<<<dim3(NB*Dd*Dd/1024, 4), 256>>>(
        q_w, k_w, v_w, o_w, qw, kw, vw, ow);

    // 2: adaLN modulation (both sets)
    adaln_mod_kernel<<<dim3(8, Bc, 2*NB), 256>>>(
        emb, axw, axb, afw, afb, mx, mxf);

    // 3: LayerNorm + modulate (both sets)
    ln_mod_kernel<<<NB*Bc*Tt + NB*Bc*Nf, 256>>>(
        x1, x2, x3, xf1, xf2, xf3, mx, mxf, xn, xfn);

    // 4: merged Q/K/V projections (tile 128x128, ldmatrix)
    gemm_qkv_kernel<<<dim3(16, 8, 9), 256, GEMM_SMEM_128>>>(
        xn, xfn, qw, q_b, kw, k_b, vw, v_b, Qp, Kp, Vp);

    // 5: attention (fp16 MMA)
    attn_f16_kernel<<<dim3(SQ/128, BHc), 256, ATTN_SMEM>>>(Qp, Kp, Vp, att);

    // 6: output projection (tile 64x128, ldmatrix, fp32 out)
    gemm_out_kernel<<<dim3(32, 8, 3), 256, GEMM_SMEM_64>>>(att, ow, o_b, out);
}